// round 9
// baseline (speedup 1.0000x reference)
#include <cuda_runtime.h>

// CrossAttention_5385888989393 — reduced channel-attention, TF32 tensor cores.
// R9: single fused cvt pass; fused dots+softmax+U kernel; GEMM7 retiled 256x128
// to halve cn re-reads. Numerics bit-identical to R8 (rel_err 6.493987e-4).

#define BATCH 8
#define NHEADS 8
#define DH 64
#define CDIM 512
#define NSP 4096

__device__ float g_G[BATCH * CDIM * CDIM];
__device__ float g_T[BATCH * NHEADS * CDIM * DH];
__device__ float g_U[BATCH * CDIM * CDIM];
__device__ float g_M[BATCH * CDIM * CDIM];
__device__ float g_cm[BATCH * CDIM * NSP];     // tf32(f_m)
__device__ float g_cn[BATCH * CDIM * NSP];     // tf32(f_n)
__device__ float g_cWk[CDIM * CDIM];           // tf32(Wkv k-half)
__device__ float g_cWout[CDIM * CDIM];         // tf32(Wout)

__device__ __forceinline__ unsigned f2tf(float f) {
    unsigned u;
    asm("cvt.rna.tf32.f32 %0, %1;" : "=r"(u) : "f"(f));
    return u;
}

__device__ __forceinline__ void cp16(void* sdst, const void* gsrc) {
    unsigned s = (unsigned)__cvta_generic_to_shared(sdst);
    asm volatile("cp.async.cg.shared.global [%0], [%1], 16;\n" :: "r"(s), "l"(gsrc));
}
__device__ __forceinline__ void cp_commit() {
    asm volatile("cp.async.commit_group;\n");
}

// ---------------------------------------------------------------------------
// Fused tf32 conversion of all four operands in one launch.
// Regions: [0,NB): f_m->cm  [NB,2NB): f_n->cn  [2NB,2NB+NW): Wkv->cWk
//          [2NB+NW, 2NB+2NW): Wout->cWout
// ---------------------------------------------------------------------------
__global__ void cvt_all_k(const float4* __restrict__ fm, uint4* __restrict__ cm,
                          const float4* __restrict__ fn, uint4* __restrict__ cn,
                          const float4* __restrict__ wkv, uint4* __restrict__ cwk,
                          const float4* __restrict__ wout, uint4* __restrict__ cwout)
{
    const int NB = BATCH * CDIM * NSP / 4;   // 4194304
    const int NW = CDIM * CDIM / 4;          // 65536
    int i = blockIdx.x * blockDim.x + threadIdx.x;
    const float4* src; uint4* dst; int off;
    if (i < NB)               { src = fm;   dst = cm;    off = i; }
    else if (i < 2 * NB)      { src = fn;   dst = cn;    off = i - NB; }
    else if (i < 2 * NB + NW) { src = wkv;  dst = cwk;   off = i - 2 * NB; }
    else                      { src = wout; dst = cwout; off = i - 2 * NB - NW; }
    float4 v = src[off];
    uint4 o;
    o.x = f2tf(v.x); o.y = f2tf(v.y); o.z = f2tf(v.z); o.w = f2tf(v.w);
    dst[off] = o;
}

// ---------------------------------------------------------------------------
// cp.async-fed TF32 GEMM (operands already tf32-rounded in gmem).
//   C[M,N] = alpha * A(M,K) * op(B) (+ bias[m]); optionally tf32-round output.
//   BK=32, 2-stage smem double buffer, 256 threads = 8 warps (WRR x WCC).
// ---------------------------------------------------------------------------
template <int BM, int BN, int WRR, int WCC, bool TRB, bool BIAS, bool CVTOUT>
__global__ void __launch_bounds__(256)
tf32gemm_ca(const float* __restrict__ A0, const float* __restrict__ B0,
            float* __restrict__ C0, const float* __restrict__ bias,
            int M, int N, int K,
            long long sA1, long long sA2, long long sB1, long long sB2,
            long long sC1, long long sC2, int B2, float alpha)
{
    constexpr int BK = 32;
    constexpr int WM = BM / WRR;
    constexpr int WN = BN / WCC;
    constexpr int IT = WM / 16;
    constexpr int JT = WN / 8;
    static_assert(WRR * WCC == 8, "8 warps");

    constexpr int AW  = BK + 4;                       // 36 words/row (144B)
    constexpr int BSR = TRB ? BN : BK;
    constexpr int BSC = TRB ? (BK + 4) : (BN + 8);
    constexpr int A_WORDS = BM * AW;
    constexpr int B_WORDS = BSR * BSC;

    constexpr int A_T4   = (BM * (BK / 4)) / 256;
    constexpr int BT_T4  = (BN * (BK / 4)) / 256;
    constexpr int BNN_T4 = (BK * (BN / 4)) / 256;
    constexpr int B_T4   = TRB ? BT_T4 : BNN_T4;
    static_assert((BM * (BK / 4)) % 256 == 0, "A tile divisible");
    static_assert((BN * (BK / 4)) % 256 == 0, "B NT tile divisible");
    static_assert((BK * (BN / 4)) % 256 == 0, "B NN tile divisible");

    extern __shared__ unsigned sm[];
    unsigned* Asm = sm;                    // [2][BM][AW]
    unsigned* Bsm = sm + 2 * A_WORDS;      // [2][BSR][BSC]

    int z = blockIdx.z;
    int i1 = z / B2, i2 = z - i1 * B2;
    const float* A  = A0 + (size_t)i1 * sA1 + (size_t)i2 * sA2;
    const float* Bp = B0 + (size_t)i1 * sB1 + (size_t)i2 * sB2;
    float*       Cp = C0 + (size_t)i1 * sC1 + (size_t)i2 * sC2;

    const int tid  = threadIdx.x;
    const int lane = tid & 31;
    const int wid  = tid >> 5;
    const int wr   = wid / WCC;
    const int wc   = wid % WCC;
    const int g    = lane >> 2;
    const int tq   = lane & 3;

    const int rowBase = blockIdx.y * BM;
    const int colBase = blockIdx.x * BN;

    float c[IT][JT][4];
    #pragma unroll
    for (int i = 0; i < IT; i++)
        #pragma unroll
        for (int j = 0; j < JT; j++)
            c[i][j][0] = c[i][j][1] = c[i][j][2] = c[i][j][3] = 0.f;

    auto load_tile = [&](int s, int k0) {
        #pragma unroll
        for (int it = 0; it < A_T4; it++) {
            int t = tid + it * 256;
            int r = t >> 3, c4 = (t & 7) << 2;
            cp16(&Asm[s * A_WORDS + r * AW + c4],
                 A + (size_t)(rowBase + r) * K + k0 + c4);
        }
        if (TRB) {
            #pragma unroll
            for (int it = 0; it < B_T4; it++) {
                int t = tid + it * 256;
                int r = t >> 3, c4 = (t & 7) << 2;
                cp16(&Bsm[s * B_WORDS + r * BSC + c4],
                     Bp + (size_t)(colBase + r) * K + k0 + c4);
            }
        } else {
            #pragma unroll
            for (int it = 0; it < B_T4; it++) {
                int t = tid + it * 256;
                int r = t / (BN / 4), c4 = (t % (BN / 4)) << 2;
                cp16(&Bsm[s * B_WORDS + r * BSC + c4],
                     Bp + (size_t)(k0 + r) * N + colBase + c4);
            }
        }
        cp_commit();
    };

    load_tile(0, 0);

    int buf = 0;
    for (int k0 = 0; k0 < K; k0 += BK) {
        const bool has_next = (k0 + BK) < K;
        if (has_next) load_tile(buf ^ 1, k0 + BK);

        if (has_next) { asm volatile("cp.async.wait_group 1;\n"); }
        else          { asm volatile("cp.async.wait_group 0;\n"); }
        __syncthreads();

        const unsigned* Ab = Asm + buf * A_WORDS;
        const unsigned* Bb = Bsm + buf * B_WORDS;

        #pragma unroll
        for (int ks = 0; ks < BK; ks += 8) {
            unsigned a[IT][4], b[JT][2];
            #pragma unroll
            for (int i = 0; i < IT; i++) {
                int m = wr * WM + i * 16;
                a[i][0] = Ab[(m + g) * AW + ks + tq];
                a[i][1] = Ab[(m + g + 8) * AW + ks + tq];
                a[i][2] = Ab[(m + g) * AW + ks + tq + 4];
                a[i][3] = Ab[(m + g + 8) * AW + ks + tq + 4];
            }
            #pragma unroll
            for (int j = 0; j < JT; j++) {
                int n = wc * WN + j * 8;
                if (TRB) {
                    b[j][0] = Bb[(n + g) * BSC + ks + tq];
                    b[j][1] = Bb[(n + g) * BSC + ks + tq + 4];
                } else {
                    b[j][0] = Bb[(ks + tq) * BSC + n + g];
                    b[j][1] = Bb[(ks + tq + 4) * BSC + n + g];
                }
            }
            #pragma unroll
            for (int i = 0; i < IT; i++)
                #pragma unroll
                for (int j = 0; j < JT; j++)
                    asm volatile(
                        "mma.sync.aligned.m16n8k8.row.col.f32.tf32.tf32.f32 "
                        "{%0,%1,%2,%3}, {%4,%5,%6,%7}, {%8,%9}, {%0,%1,%2,%3};\n"
                        : "+f"(c[i][j][0]), "+f"(c[i][j][1]),
                          "+f"(c[i][j][2]), "+f"(c[i][j][3])
                        : "r"(a[i][0]), "r"(a[i][1]), "r"(a[i][2]), "r"(a[i][3]),
                          "r"(b[j][0]), "r"(b[j][1]));
        }
        __syncthreads();
        buf ^= 1;
    }

    #pragma unroll
    for (int i = 0; i < IT; i++) {
        int row = rowBase + wr * WM + i * 16 + g;
        float bv0 = BIAS ? bias[row] : 0.f;
        float bv1 = BIAS ? bias[row + 8] : 0.f;
        #pragma unroll
        for (int j = 0; j < JT; j++) {
            int col = colBase + wc * WN + j * 8 + 2 * tq;
            float v00 = alpha * c[i][j][0] + bv0;
            float v01 = alpha * c[i][j][1] + bv0;
            float v10 = alpha * c[i][j][2] + bv1;
            float v11 = alpha * c[i][j][3] + bv1;
            if (CVTOUT) {
                v00 = __uint_as_float(f2tf(v00));
                v01 = __uint_as_float(f2tf(v01));
                v10 = __uint_as_float(f2tf(v10));
                v11 = __uint_as_float(f2tf(v11));
            }
            Cp[(size_t)row * N + col]           = v00;
            Cp[(size_t)row * N + col + 1]       = v01;
            Cp[(size_t)(row + 8) * N + col]     = v10;
            Cp[(size_t)(row + 8) * N + col + 1] = v11;
        }
    }
}

// ---------------------------------------------------------------------------
// Fused middle: dots = (Wq_h @ T_bh)*scale ; attn = softmax(dots) ;
//               U_bh = attn @ Wv_h (tf32-rounded out).
// One CTA per (b,h); 256 threads; thread owns a 4x4 output block (tm,tn).
// Accumulation order per element is strictly ascending k — bit-identical to
// the previous sgemm path.
// ---------------------------------------------------------------------------
__global__ void __launch_bounds__(256)
attn_mid(const float* __restrict__ Wq, const float* __restrict__ T,
         const float* __restrict__ WkvV, float* __restrict__ U)
{
    const int z = blockIdx.x;               // b*NHEADS + h
    const int b = z / NHEADS, h = z % NHEADS;
    const float* Aq = Wq  + (size_t)h * DH * CDIM;                     // 64x512
    const float* Tb = T   + (size_t)z * CDIM * DH;                     // 512x64
    const float* Wv = WkvV + (size_t)h * DH * CDIM;                    // 64x512
    float* Ub = U + (size_t)b * CDIM * CDIM + (size_t)h * DH * CDIM;   // 64x512

    extern __shared__ float s[];
    float* sA  = s;            // [64][68] — Wq slab, later Wv slab
    float* sB  = s + 4352;     // [64][68] — T slab
    float* sAt = s + 8704;     // [64][68] — dots / attn

    const int tid  = threadIdx.x;
    const int tm   = tid >> 4;     // 0..15
    const int tn   = tid & 15;     // 0..15
    const int lane = tid & 31;
    const int wrp  = tid >> 5;

    // ---- Phase 1: dots = Wq_h @ T_bh  (K=512, k-slabs of 64, ascending)
    float acc[4][4] = {};
    for (int k0 = 0; k0 < CDIM; k0 += 64) {
        #pragma unroll
        for (int it = 0; it < 4; it++) {
            int t = tid + it * 256;
            int r = t >> 4, c4 = (t & 15) << 2;
            float4 v = *(const float4*)(Aq + (size_t)r * CDIM + k0 + c4);
            sA[r * 68 + c4 + 0] = v.x; sA[r * 68 + c4 + 1] = v.y;
            sA[r * 68 + c4 + 2] = v.z; sA[r * 68 + c4 + 3] = v.w;
        }
        #pragma unroll
        for (int it = 0; it < 4; it++) {
            int t = tid + it * 256;
            int r = t >> 4, c4 = (t & 15) << 2;
            float4 v = *(const float4*)(Tb + (size_t)(k0 + r) * DH + c4);
            sB[r * 68 + c4 + 0] = v.x; sB[r * 68 + c4 + 1] = v.y;
            sB[r * 68 + c4 + 2] = v.z; sB[r * 68 + c4 + 3] = v.w;
        }
        __syncthreads();
        for (int kk = 0; kk < 64; kk++) {
            float ra[4], rb[4];
            #pragma unroll
            for (int ii = 0; ii < 4; ii++) ra[ii] = sA[(tm * 4 + ii) * 68 + kk];
            #pragma unroll
            for (int jj = 0; jj < 4; jj++) rb[jj] = sB[kk * 68 + tn * 4 + jj];
            #pragma unroll
            for (int ii = 0; ii < 4; ii++)
                #pragma unroll
                for (int jj = 0; jj < 4; jj++)
                    acc[ii][jj] = fmaf(ra[ii], rb[jj], acc[ii][jj]);
        }
        __syncthreads();
    }
    #pragma unroll
    for (int ii = 0; ii < 4; ii++)
        #pragma unroll
        for (int jj = 0; jj < 4; jj++)
            sAt[(tm * 4 + ii) * 68 + tn * 4 + jj] = 0.125f * acc[ii][jj];
    __syncthreads();

    // ---- Phase 2: softmax rows (identical op sequence to softmax64)
    for (int row = wrp; row < 64; row += 8) {
        float* r = sAt + row * 68;
        float a = r[lane];
        float bb = r[lane + 32];
        float m = fmaxf(a, bb);
        #pragma unroll
        for (int o = 16; o > 0; o >>= 1) m = fmaxf(m, __shfl_xor_sync(0xffffffffu, m, o));
        float e1 = __expf(a - m);
        float e2 = __expf(bb - m);
        float ss = e1 + e2;
        #pragma unroll
        for (int o = 16; o > 0; o >>= 1) ss += __shfl_xor_sync(0xffffffffu, ss, o);
        float inv = 1.0f / ss;
        r[lane]      = e1 * inv;
        r[lane + 32] = e2 * inv;
    }
    __syncthreads();

    // ---- Phase 3: U = attn @ Wv_h  (K=64 ascending), tf32-rounded out
    for (int n0 = 0; n0 < CDIM; n0 += 64) {
        #pragma unroll
        for (int it = 0; it < 4; it++) {
            int t = tid + it * 256;
            int r = t >> 4, c4 = (t & 15) << 2;
            float4 v = *(const float4*)(Wv + (size_t)r * CDIM + n0 + c4);
            sA[r * 68 + c4 + 0] = v.x; sA[r * 68 + c4 + 1] = v.y;
            sA[r * 68 + c4 + 2] = v.z; sA[r * 68 + c4 + 3] = v.w;
        }
        __syncthreads();
        float u[4][4] = {};
        for (int k = 0; k < 64; k++) {
            float ra[4], rb[4];
            #pragma unroll
            for (int ii = 0; ii < 4; ii++) ra[ii] = sAt[(tm * 4 + ii) * 68 + k];
            #pragma unroll
            for (int jj = 0; jj < 4; jj++) rb[jj] = sA[k * 68 + tn * 4 + jj];
            #pragma unroll
            for (int ii = 0; ii < 4; ii++)
                #pragma unroll
                for (int jj = 0; jj < 4; jj++)
                    u[ii][jj] = fmaf(ra[ii], rb[jj], u[ii][jj]);
        }
        #pragma unroll
        for (int ii = 0; ii < 4; ii++)
            #pragma unroll
            for (int jj = 0; jj < 4; jj++)
                Ub[(size_t)(tm * 4 + ii) * CDIM + n0 + tn * 4 + jj] =
                    __uint_as_float(f2tf(u[ii][jj]));
        __syncthreads();
    }
}

extern "C" void kernel_launch(void* const* d_in, const int* in_sizes, int n_in,
                              void* d_out, int out_size)
{
    const float* f_m  = (const float*)d_in[0];
    const float* f_n  = (const float*)d_in[1];
    const float* Wq   = (const float*)d_in[2];
    const float* Wkv  = (const float*)d_in[3];
    const float* Wout = (const float*)d_in[4];
    const float* bout = (const float*)d_in[5];
    float* out = (float*)d_out;

    float *G, *T, *U, *Mm, *cm, *cn, *cWk, *cWout;
    cudaGetSymbolAddress((void**)&G,     g_G);
    cudaGetSymbolAddress((void**)&T,     g_T);
    cudaGetSymbolAddress((void**)&U,     g_U);
    cudaGetSymbolAddress((void**)&Mm,    g_M);
    cudaGetSymbolAddress((void**)&cm,    g_cm);
    cudaGetSymbolAddress((void**)&cn,    g_cn);
    cudaGetSymbolAddress((void**)&cWk,   g_cWk);
    cudaGetSymbolAddress((void**)&cWout, g_cWout);

    const long long CF  = (long long)CDIM * NSP;
    const long long CC  = (long long)CDIM * CDIM;
    const long long THD = (long long)CDIM * DH;

    constexpr int SM_128_NT = (2 * 128 * 36 + 2 * 128 * 36) * 4;   // 73728
    constexpr int SM_64_NT  = (2 * 64 * 36 + 2 * 64 * 36) * 4;     // 36864
    constexpr int SM_128_NN = (2 * 128 * 36 + 2 * 32 * 136) * 4;   // 71680
    constexpr int SM_256_NN = (2 * 256 * 36 + 2 * 32 * 136) * 4;   // 108544
    constexpr int SM_ATTN   = 3 * 4352 * 4;                        // 52224

    cudaFuncSetAttribute(tf32gemm_ca<128, 128, 2, 4, true, false, true>,
                         cudaFuncAttributeMaxDynamicSharedMemorySize, SM_128_NT);
    cudaFuncSetAttribute(tf32gemm_ca<64, 64, 2, 4, true, false, false>,
                         cudaFuncAttributeMaxDynamicSharedMemorySize, SM_64_NT);
    cudaFuncSetAttribute(tf32gemm_ca<128, 128, 2, 4, false, false, true>,
                         cudaFuncAttributeMaxDynamicSharedMemorySize, SM_128_NN);
    cudaFuncSetAttribute(tf32gemm_ca<256, 128, 4, 2, false, true, false>,
                         cudaFuncAttributeMaxDynamicSharedMemorySize, SM_256_NN);
    cudaFuncSetAttribute(attn_mid,
                         cudaFuncAttributeMaxDynamicSharedMemorySize, SM_ATTN);

    // 0) all tf32 pre-conversions in ONE launch
    {
        const int NB = BATCH * CDIM * NSP / 4;     // 4194304
        const int NW = CDIM * CDIM / 4;            // 65536
        int total = 2 * NB + 2 * NW;               // 8519680 = 33280*256
        cvt_all_k<<<total / 256, 256>>>(
            (const float4*)f_m, (uint4*)cm, (const float4*)f_n, (uint4*)cn,
            (const float4*)Wkv, (uint4*)cWk, (const float4*)Wout, (uint4*)cWout);
    }

    // 1) G[b] = cm[b] @ cn[b]^T   (NT, K=4096), out tf32-rounded
    tf32gemm_ca<128, 128, 2, 4, true, false, true>
        <<<dim3(4, 4, BATCH), 256, SM_128_NT>>>(
        cm, cn, G, nullptr, CDIM, CDIM, NSP,
        CF, 0, CF, 0, CC, 0, 1, 1.0f);

    // 2) T[b,h] = G[b] @ cWk_h^T  (NT, K=512), out fp32
    tf32gemm_ca<64, 64, 2, 4, true, false, false>
        <<<dim3(1, 8, BATCH * NHEADS), 256, SM_64_NT>>>(
        G, cWk, T, nullptr, CDIM, DH, CDIM,
        CC, 0, 0, (long long)DH * CDIM, (long long)NHEADS * THD, THD,
        NHEADS, 1.0f);

    // 3-5) fused dots + softmax + U   (one CTA per (b,h))
    attn_mid<<<BATCH * NHEADS, 256, SM_ATTN>>>(
        Wq, T, Wkv + (size_t)CDIM * CDIM, U);

    // 6) M[b] = cWout @ U[b]   (NN, K=512), out tf32-rounded
    tf32gemm_ca<128, 128, 2, 4, false, false, true>
        <<<dim3(4, 4, BATCH), 256, SM_128_NN>>>(
        cWout, U, Mm, nullptr, CDIM, CDIM, CDIM,
        0, 0, CC, 0, CC, 0, 1, 1.0f);

    // 7) out[b] = M[b] @ cn[b] + bout  (NN, K=512, bias), 256x128 tiles
    tf32gemm_ca<256, 128, 4, 2, false, true, false>
        <<<dim3(32, 2, BATCH), 256, SM_256_NN>>>(
        Mm, cn, out, bout, CDIM, NSP, CDIM,
        CC, 0, CF, 0, CF, 0, 1, 1.0f);
}

// round 12
// speedup vs baseline: 1.0201x; 1.0201x over previous
#include <cuda_runtime.h>

// CrossAttention_5385888989393 — reduced channel-attention, TF32 tensor cores.
// R10: middle split back to (dots+softmax fused @64 CTAs) + (U gemm @512 CTAs);
// GEMM1 converts A (f_m) in-loop via LDG+f2tf+STS (cm buffer eliminated).
// Numerics bit-identical to R8/R9 (rel_err 6.493987e-4).

#define BATCH 8
#define NHEADS 8
#define DH 64
#define CDIM 512
#define NSP 4096

__device__ float g_G[BATCH * CDIM * CDIM];
__device__ float g_T[BATCH * NHEADS * CDIM * DH];
__device__ float g_dots[BATCH * NHEADS * DH * DH];
__device__ float g_U[BATCH * CDIM * CDIM];
__device__ float g_M[BATCH * CDIM * CDIM];
__device__ float g_cn[BATCH * CDIM * NSP];     // tf32(f_n)
__device__ float g_cWk[CDIM * CDIM];           // tf32(Wkv k-half)
__device__ float g_cWout[CDIM * CDIM];         // tf32(Wout)

__device__ __forceinline__ unsigned f2tf(float f) {
    unsigned u;
    asm("cvt.rna.tf32.f32 %0, %1;" : "=r"(u) : "f"(f));
    return u;
}

__device__ __forceinline__ void cp16(void* sdst, const void* gsrc) {
    unsigned s = (unsigned)__cvta_generic_to_shared(sdst);
    asm volatile("cp.async.cg.shared.global [%0], [%1], 16;\n" :: "r"(s), "l"(gsrc));
}
__device__ __forceinline__ void cp_commit() {
    asm volatile("cp.async.commit_group;\n");
}

// ---------------------------------------------------------------------------
// Fused tf32 conversion (f_n, Wkv k-half, Wout) in one launch. f_m is now
// converted in-loop by GEMM1 (single consumer).
// ---------------------------------------------------------------------------
__global__ void cvt_all_k(const float4* __restrict__ fn, uint4* __restrict__ cn,
                          const float4* __restrict__ wkv, uint4* __restrict__ cwk,
                          const float4* __restrict__ wout, uint4* __restrict__ cwout)
{
    const int NB = BATCH * CDIM * NSP / 4;   // 4194304
    const int NW = CDIM * CDIM / 4;          // 65536
    int i = blockIdx.x * blockDim.x + threadIdx.x;
    const float4* src; uint4* dst; int off;
    if (i < NB)          { src = fn;   dst = cn;    off = i; }
    else if (i < NB + NW){ src = wkv;  dst = cwk;   off = i - NB; }
    else                 { src = wout; dst = cwout; off = i - NB - NW; }
    float4 v = src[off];
    uint4 o;
    o.x = f2tf(v.x); o.y = f2tf(v.y); o.z = f2tf(v.z); o.w = f2tf(v.w);
    dst[off] = o;
}

// ---------------------------------------------------------------------------
// cp.async-fed TF32 GEMM. CVTA=true: A is raw fp32 in gmem, loaded via LDG
// (prefetched a tile ahead) and tf32-rounded at STS; B always via cp.async
// from pre-rounded gmem. CVTA=false: both operands cp.async (pre-rounded).
//   BK=32, 2-stage smem double buffer, 256 threads = 8 warps (WRR x WCC).
// ---------------------------------------------------------------------------
template <int BM, int BN, int WRR, int WCC, bool TRB, bool BIAS, bool CVTOUT, bool CVTA>
__global__ void __launch_bounds__(256)
tf32gemm_ca(const float* __restrict__ A0, const float* __restrict__ B0,
            float* __restrict__ C0, const float* __restrict__ bias,
            int M, int N, int K,
            long long sA1, long long sA2, long long sB1, long long sB2,
            long long sC1, long long sC2, int B2, float alpha)
{
    constexpr int BK = 32;
    constexpr int WM = BM / WRR;
    constexpr int WN = BN / WCC;
    constexpr int IT = WM / 16;
    constexpr int JT = WN / 8;
    static_assert(WRR * WCC == 8, "8 warps");

    constexpr int AW  = BK + 4;
    constexpr int BSR = TRB ? BN : BK;
    constexpr int BSC = TRB ? (BK + 4) : (BN + 8);
    constexpr int A_WORDS = BM * AW;
    constexpr int B_WORDS = BSR * BSC;

    constexpr int A_T4   = (BM * (BK / 4)) / 256;
    constexpr int BT_T4  = (BN * (BK / 4)) / 256;
    constexpr int BNN_T4 = (BK * (BN / 4)) / 256;
    constexpr int B_T4   = TRB ? BT_T4 : BNN_T4;
    static_assert((BM * (BK / 4)) % 256 == 0, "A tile divisible");
    static_assert((BN * (BK / 4)) % 256 == 0, "B NT tile divisible");
    static_assert((BK * (BN / 4)) % 256 == 0, "B NN tile divisible");

    extern __shared__ unsigned sm[];
    unsigned* Asm = sm;                    // [2][BM][AW]
    unsigned* Bsm = sm + 2 * A_WORDS;      // [2][BSR][BSC]

    int z = blockIdx.z;
    int i1 = z / B2, i2 = z - i1 * B2;
    const float* A  = A0 + (size_t)i1 * sA1 + (size_t)i2 * sA2;
    const float* Bp = B0 + (size_t)i1 * sB1 + (size_t)i2 * sB2;
    float*       Cp = C0 + (size_t)i1 * sC1 + (size_t)i2 * sC2;

    const int tid  = threadIdx.x;
    const int lane = tid & 31;
    const int wid  = tid >> 5;
    const int wr   = wid / WCC;
    const int wc   = wid % WCC;
    const int g    = lane >> 2;
    const int tq   = lane & 3;

    const int rowBase = blockIdx.y * BM;
    const int colBase = blockIdx.x * BN;

    float c[IT][JT][4];
    #pragma unroll
    for (int i = 0; i < IT; i++)
        #pragma unroll
        for (int j = 0; j < JT; j++)
            c[i][j][0] = c[i][j][1] = c[i][j][2] = c[i][j][3] = 0.f;

    float4 pa[CVTA ? A_T4 : 1];

    // A via cp.async (pre-rounded gmem) for stage s
    auto load_A_async = [&](int s, int k0) {
        #pragma unroll
        for (int it = 0; it < A_T4; it++) {
            int t = tid + it * 256;
            int r = t >> 3, c4 = (t & 7) << 2;
            cp16(&Asm[s * A_WORDS + r * AW + c4],
                 A + (size_t)(rowBase + r) * K + k0 + c4);
        }
    };
    // A via LDG into regs (raw fp32)
    auto load_A_regs = [&](int k0) {
        #pragma unroll
        for (int it = 0; it < A_T4; it++) {
            int t = tid + it * 256;
            int r = t >> 3, c4 = (t & 7) << 2;
            pa[it] = *reinterpret_cast<const float4*>(
                A + (size_t)(rowBase + r) * K + k0 + c4);
        }
    };
    // STS A regs -> stage s with f2tf
    auto sts_A = [&](int s) {
        #pragma unroll
        for (int it = 0; it < A_T4; it++) {
            int t = tid + it * 256;
            int r = t >> 3, c4 = (t & 7) << 2;
            unsigned* dst = &Asm[s * A_WORDS + r * AW + c4];
            dst[0] = f2tf(pa[it].x); dst[1] = f2tf(pa[it].y);
            dst[2] = f2tf(pa[it].z); dst[3] = f2tf(pa[it].w);
        }
    };
    auto load_B = [&](int s, int k0) {
        if (TRB) {
            #pragma unroll
            for (int it = 0; it < B_T4; it++) {
                int t = tid + it * 256;
                int r = t >> 3, c4 = (t & 7) << 2;
                cp16(&Bsm[s * B_WORDS + r * BSC + c4],
                     Bp + (size_t)(colBase + r) * K + k0 + c4);
            }
        } else {
            #pragma unroll
            for (int it = 0; it < B_T4; it++) {
                int t = tid + it * 256;
                int r = t / (BN / 4), c4 = (t % (BN / 4)) << 2;
                cp16(&Bsm[s * B_WORDS + r * BSC + c4],
                     Bp + (size_t)(k0 + r) * N + colBase + c4);
            }
        }
    };

    // ---- prologue
    if (CVTA) {
        load_A_regs(0);
        load_B(0, 0);
        cp_commit();
        sts_A(0);
        asm volatile("cp.async.wait_group 0;\n");
        __syncthreads();
    } else {
        load_A_async(0, 0);
        load_B(0, 0);
        cp_commit();
    }

    int buf = 0;
    for (int k0 = 0; k0 < K; k0 += BK) {
        const bool has_next = (k0 + BK) < K;
        if (has_next) {
            if (CVTA) {
                load_A_regs(k0 + BK);
                load_B(buf ^ 1, k0 + BK);
                cp_commit();
            } else {
                load_A_async(buf ^ 1, k0 + BK);
                load_B(buf ^ 1, k0 + BK);
                cp_commit();
            }
        }

        if (!CVTA) {
            if (has_next) { asm volatile("cp.async.wait_group 1;\n"); }
            else          { asm volatile("cp.async.wait_group 0;\n"); }
            __syncthreads();
        }
        // (CVTA path: stage `buf` already complete & synced at loop entry)

        const unsigned* Ab = Asm + buf * A_WORDS;
        const unsigned* Bb = Bsm + buf * B_WORDS;

        #pragma unroll
        for (int ks = 0; ks < BK; ks += 8) {
            unsigned a[IT][4], b[JT][2];
            #pragma unroll
            for (int i = 0; i < IT; i++) {
                int m = wr * WM + i * 16;
                a[i][0] = Ab[(m + g) * AW + ks + tq];
                a[i][1] = Ab[(m + g + 8) * AW + ks + tq];
                a[i][2] = Ab[(m + g) * AW + ks + tq + 4];
                a[i][3] = Ab[(m + g + 8) * AW + ks + tq + 4];
            }
            #pragma unroll
            for (int j = 0; j < JT; j++) {
                int n = wc * WN + j * 8;
                if (TRB) {
                    b[j][0] = Bb[(n + g) * BSC + ks + tq];
                    b[j][1] = Bb[(n + g) * BSC + ks + tq + 4];
                } else {
                    b[j][0] = Bb[(ks + tq) * BSC + n + g];
                    b[j][1] = Bb[(ks + tq + 4) * BSC + n + g];
                }
            }
            #pragma unroll
            for (int i = 0; i < IT; i++)
                #pragma unroll
                for (int j = 0; j < JT; j++)
                    asm volatile(
                        "mma.sync.aligned.m16n8k8.row.col.f32.tf32.tf32.f32 "
                        "{%0,%1,%2,%3}, {%4,%5,%6,%7}, {%8,%9}, {%0,%1,%2,%3};\n"
                        : "+f"(c[i][j][0]), "+f"(c[i][j][1]),
                          "+f"(c[i][j][2]), "+f"(c[i][j][3])
                        : "r"(a[i][0]), "r"(a[i][1]), "r"(a[i][2]), "r"(a[i][3]),
                          "r"(b[j][0]), "r"(b[j][1]));
        }

        if (CVTA) {
            __syncthreads();                 // reads of `buf` done
            if (has_next) {
                sts_A(buf ^ 1);              // write next A stage
                asm volatile("cp.async.wait_group 0;\n");   // next B landed
                __syncthreads();             // next stage visible
            }
        } else {
            __syncthreads();
        }
        buf ^= 1;
    }

    #pragma unroll
    for (int i = 0; i < IT; i++) {
        int row = rowBase + wr * WM + i * 16 + g;
        float bv0 = BIAS ? bias[row] : 0.f;
        float bv1 = BIAS ? bias[row + 8] : 0.f;
        #pragma unroll
        for (int j = 0; j < JT; j++) {
            int col = colBase + wc * WN + j * 8 + 2 * tq;
            float v00 = alpha * c[i][j][0] + bv0;
            float v01 = alpha * c[i][j][1] + bv0;
            float v10 = alpha * c[i][j][2] + bv1;
            float v11 = alpha * c[i][j][3] + bv1;
            if (CVTOUT) {
                v00 = __uint_as_float(f2tf(v00));
                v01 = __uint_as_float(f2tf(v01));
                v10 = __uint_as_float(f2tf(v10));
                v11 = __uint_as_float(f2tf(v11));
            }
            Cp[(size_t)row * N + col]           = v00;
            Cp[(size_t)row * N + col + 1]       = v01;
            Cp[(size_t)(row + 8) * N + col]     = v10;
            Cp[(size_t)(row + 8) * N + col + 1] = v11;
        }
    }
}

// ---------------------------------------------------------------------------
// Fused dots+softmax: dots = (Wq_h @ T_bh)*scale; attn = softmax rows -> gmem.
// One CTA per (b,h); ascending-k accumulation (bit-identical to sgemm path).
// ---------------------------------------------------------------------------
__global__ void __launch_bounds__(256)
attn_ds(const float* __restrict__ Wq, const float* __restrict__ T,
        float* __restrict__ dots)
{
    const int z = blockIdx.x;               // b*NHEADS + h
    const int h = z % NHEADS;
    const float* Aq = Wq + (size_t)h * DH * CDIM;       // 64x512
    const float* Tb = T  + (size_t)z * CDIM * DH;       // 512x64
    float* Db = dots + (size_t)z * DH * DH;             // 64x64

    extern __shared__ float s[];
    float* sA  = s;            // [64][68]
    float* sB  = s + 4352;     // [64][68]
    float* sAt = s + 8704;     // [64][68]

    const int tid  = threadIdx.x;
    const int tm   = tid >> 4;
    const int tn   = tid & 15;
    const int lane = tid & 31;
    const int wrp  = tid >> 5;

    float acc[4][4] = {};
    for (int k0 = 0; k0 < CDIM; k0 += 64) {
        #pragma unroll
        for (int it = 0; it < 4; it++) {
            int t = tid + it * 256;
            int r = t >> 4, c4 = (t & 15) << 2;
            float4 v = *(const float4*)(Aq + (size_t)r * CDIM + k0 + c4);
            sA[r * 68 + c4 + 0] = v.x; sA[r * 68 + c4 + 1] = v.y;
            sA[r * 68 + c4 + 2] = v.z; sA[r * 68 + c4 + 3] = v.w;
        }
        #pragma unroll
        for (int it = 0; it < 4; it++) {
            int t = tid + it * 256;
            int r = t >> 4, c4 = (t & 15) << 2;
            float4 v = *(const float4*)(Tb + (size_t)(k0 + r) * DH + c4);
            sB[r * 68 + c4 + 0] = v.x; sB[r * 68 + c4 + 1] = v.y;
            sB[r * 68 + c4 + 2] = v.z; sB[r * 68 + c4 + 3] = v.w;
        }
        __syncthreads();
        for (int kk = 0; kk < 64; kk++) {
            float ra[4], rb[4];
            #pragma unroll
            for (int ii = 0; ii < 4; ii++) ra[ii] = sA[(tm * 4 + ii) * 68 + kk];
            #pragma unroll
            for (int jj = 0; jj < 4; jj++) rb[jj] = sB[kk * 68 + tn * 4 + jj];
            #pragma unroll
            for (int ii = 0; ii < 4; ii++)
                #pragma unroll
                for (int jj = 0; jj < 4; jj++)
                    acc[ii][jj] = fmaf(ra[ii], rb[jj], acc[ii][jj]);
        }
        __syncthreads();
    }
    #pragma unroll
    for (int ii = 0; ii < 4; ii++)
        #pragma unroll
        for (int jj = 0; jj < 4; jj++)
            sAt[(tm * 4 + ii) * 68 + tn * 4 + jj] = 0.125f * acc[ii][jj];
    __syncthreads();

    // softmax rows (identical op sequence to softmax64), write to gmem
    for (int row = wrp; row < 64; row += 8) {
        float* r = sAt + row * 68;
        float a = r[lane];
        float bb = r[lane + 32];
        float m = fmaxf(a, bb);
        #pragma unroll
        for (int o = 16; o > 0; o >>= 1) m = fmaxf(m, __shfl_xor_sync(0xffffffffu, m, o));
        float e1 = __expf(a - m);
        float e2 = __expf(bb - m);
        float ss = e1 + e2;
        #pragma unroll
        for (int o = 16; o > 0; o >>= 1) ss += __shfl_xor_sync(0xffffffffu, ss, o);
        float inv = 1.0f / ss;
        Db[row * 64 + lane]      = e1 * inv;
        Db[row * 64 + lane + 32] = e2 * inv;
    }
}

// ---------------------------------------------------------------------------
// fp32 SGEMM (U = attn @ Wv), optional tf32-rounded output. 64x64 tiles.
// ---------------------------------------------------------------------------
template <int BM, int BN, int BK, int TM, int TN, bool TRB, bool BIAS, bool CVTOUT>
__global__ void __launch_bounds__((BM / TM) * (BN / TN))
sgemm(const float* __restrict__ A0, const float* __restrict__ B0,
      float* __restrict__ C0, const float* __restrict__ bias,
      int M, int N, int K,
      long long sA1, long long sA2, long long sB1, long long sB2,
      long long sC1, long long sC2, int B2, float alpha)
{
    constexpr int THREADS = (BM / TM) * (BN / TN);
    constexpr int A_TRIPS = (BM * BK / 4) / THREADS;
    constexpr int B_TRIPS = (BN * BK / 4) / THREADS;

    int z = blockIdx.z;
    int i1 = z / B2;
    int i2 = z - i1 * B2;
    const float* A  = A0 + (size_t)i1 * sA1 + (size_t)i2 * sA2;
    const float* Bp = B0 + (size_t)i1 * sB1 + (size_t)i2 * sB2;
    float*       Cp = C0 + (size_t)i1 * sC1 + (size_t)i2 * sC2;

    __shared__ float As[BK][BM + 4];
    __shared__ float Bs[BK][BN + 4];

    const int tid = threadIdx.x;
    const int tn  = tid % (BN / TN);
    const int tm  = tid / (BN / TN);
    const int rowC = blockIdx.y * BM + tm * TM;
    const int colC = blockIdx.x * BN + tn * TN;

    float acc[TM][TN] = {};

    for (int k0 = 0; k0 < K; k0 += BK) {
        #pragma unroll
        for (int it = 0; it < A_TRIPS; it++) {
            int t  = tid + it * THREADS;
            int r  = t / (BK / 4);
            int c4 = (t % (BK / 4)) * 4;
            float4 v = *reinterpret_cast<const float4*>(
                A + (size_t)(blockIdx.y * BM + r) * K + k0 + c4);
            As[c4 + 0][r] = v.x; As[c4 + 1][r] = v.y;
            As[c4 + 2][r] = v.z; As[c4 + 3][r] = v.w;
        }
        if (TRB) {
            #pragma unroll
            for (int it = 0; it < B_TRIPS; it++) {
                int t  = tid + it * THREADS;
                int r  = t / (BK / 4);
                int c4 = (t % (BK / 4)) * 4;
                float4 v = *reinterpret_cast<const float4*>(
                    Bp + (size_t)(blockIdx.x * BN + r) * K + k0 + c4);
                Bs[c4 + 0][r] = v.x; Bs[c4 + 1][r] = v.y;
                Bs[c4 + 2][r] = v.z; Bs[c4 + 3][r] = v.w;
            }
        } else {
            #pragma unroll
            for (int it = 0; it < B_TRIPS; it++) {
                int t  = tid + it * THREADS;
                int r  = t / (BN / 4);
                int c4 = (t % (BN / 4)) * 4;
                float4 v = *reinterpret_cast<const float4*>(
                    Bp + (size_t)(k0 + r) * N + blockIdx.x * BN + c4);
                *reinterpret_cast<float4*>(&Bs[r][c4]) = v;
            }
        }
        __syncthreads();

        #pragma unroll
        for (int k = 0; k < BK; k++) {
            float ra[TM], rb[TN];
            #pragma unroll
            for (int i = 0; i < TM; i++) ra[i] = As[k][tm * TM + i];
            #pragma unroll
            for (int j = 0; j < TN; j++) rb[j] = Bs[k][tn * TN + j];
            #pragma unroll
            for (int i = 0; i < TM; i++)
                #pragma unroll
                for (int j = 0; j < TN; j++)
                    acc[i][j] = fmaf(ra[i], rb[j], acc[i][j]);
        }
        __syncthreads();
    }

    #pragma unroll
    for (int i = 0; i < TM; i++) {
        float bv = BIAS ? bias[rowC + i] : 0.0f;
        #pragma unroll
        for (int j = 0; j < TN; j++) {
            float v = alpha * acc[i][j] + bv;
            if (CVTOUT) v = __uint_as_float(f2tf(v));
            Cp[(size_t)(rowC + i) * N + colC + j] = v;
        }
    }
}

extern "C" void kernel_launch(void* const* d_in, const int* in_sizes, int n_in,
                              void* d_out, int out_size)
{
    const float* f_m  = (const float*)d_in[0];
    const float* f_n  = (const float*)d_in[1];
    const float* Wq   = (const float*)d_in[2];
    const float* Wkv  = (const float*)d_in[3];
    const float* Wout = (const float*)d_in[4];
    const float* bout = (const float*)d_in[5];
    float* out = (float*)d_out;

    float *G, *T, *dots, *U, *Mm, *cn, *cWk, *cWout;
    cudaGetSymbolAddress((void**)&G,     g_G);
    cudaGetSymbolAddress((void**)&T,     g_T);
    cudaGetSymbolAddress((void**)&dots,  g_dots);
    cudaGetSymbolAddress((void**)&U,     g_U);
    cudaGetSymbolAddress((void**)&Mm,    g_M);
    cudaGetSymbolAddress((void**)&cn,    g_cn);
    cudaGetSymbolAddress((void**)&cWk,   g_cWk);
    cudaGetSymbolAddress((void**)&cWout, g_cWout);

    const long long CF  = (long long)CDIM * NSP;
    const long long CC  = (long long)CDIM * CDIM;
    const long long THD = (long long)CDIM * DH;

    constexpr int SM_128_NT = (2 * 128 * 36 + 2 * 128 * 36) * 4;   // 73728
    constexpr int SM_64_NT  = (2 * 64 * 36 + 2 * 64 * 36) * 4;     // 36864
    constexpr int SM_128_NN = (2 * 128 * 36 + 2 * 32 * 136) * 4;   // 71680
    constexpr int SM_256_NN = (2 * 256 * 36 + 2 * 32 * 136) * 4;   // 108544
    constexpr int SM_ATTN   = 3 * 4352 * 4;                        // 52224

    cudaFuncSetAttribute(tf32gemm_ca<128, 128, 2, 4, true, false, true, true>,
                         cudaFuncAttributeMaxDynamicSharedMemorySize, SM_128_NT);
    cudaFuncSetAttribute(tf32gemm_ca<64, 64, 2, 4, true, false, false, false>,
                         cudaFuncAttributeMaxDynamicSharedMemorySize, SM_64_NT);
    cudaFuncSetAttribute(tf32gemm_ca<128, 128, 2, 4, false, false, true, false>,
                         cudaFuncAttributeMaxDynamicSharedMemorySize, SM_128_NN);
    cudaFuncSetAttribute(tf32gemm_ca<256, 128, 4, 2, false, true, false, false>,
                         cudaFuncAttributeMaxDynamicSharedMemorySize, SM_256_NN);
    cudaFuncSetAttribute(attn_ds,
                         cudaFuncAttributeMaxDynamicSharedMemorySize, SM_ATTN);

    // 0) tf32 pre-conversions (f_n, Wkv k-half, Wout) in ONE launch
    {
        const int NB = BATCH * CDIM * NSP / 4;     // 4194304
        const int NW = CDIM * CDIM / 4;            // 65536
        int total = NB + 2 * NW;                   // 4325376 = 16896*256
        cvt_all_k<<<total / 256, 256>>>(
            (const float4*)f_n, (uint4*)cn,
            (const float4*)Wkv, (uint4*)cWk, (const float4*)Wout, (uint4*)cWout);
    }

    // 1) G[b] = tf32(f_m[b]) @ cn[b]^T  (NT, K=4096), A cvt in-loop, out tf32
    tf32gemm_ca<128, 128, 2, 4, true, false, true, true>
        <<<dim3(4, 4, BATCH), 256, SM_128_NT>>>(
        f_m, cn, G, nullptr, CDIM, CDIM, NSP,
        CF, 0, CF, 0, CC, 0, 1, 1.0f);

    // 2) T[b,h] = G[b] @ cWk_h^T  (NT, K=512), out fp32
    tf32gemm_ca<64, 64, 2, 4, true, false, false, false>
        <<<dim3(1, 8, BATCH * NHEADS), 256, SM_64_NT>>>(
        G, cWk, T, nullptr, CDIM, DH, CDIM,
        CC, 0, 0, (long long)DH * CDIM, (long long)NHEADS * THD, THD,
        NHEADS, 1.0f);

    // 3-4) fused dots + softmax -> attn in gmem  (64 CTAs)
    attn_ds<<<BATCH * NHEADS, 256, SM_ATTN>>>(Wq, T, dots);

    // 5) U[b] = attn[b,h] @ Wv_h  (NN, K=64), 512 CTAs, out tf32-rounded
    sgemm<64, 64, 16, 4, 4, false, false, true>
        <<<dim3(8, 1, BATCH * NHEADS), 256>>>(
        dots, Wkv + (size_t)CDIM * CDIM, U, nullptr, DH, CDIM, DH,
        (long long)NHEADS * DH * DH, (long long)DH * DH,
        0, (long long)DH * CDIM,
        CC, (long long)DH * CDIM,
        NHEADS, 1.0f);

    // 6) M[b] = cWout @ U[b]   (NN, K=512), out tf32-rounded
    tf32gemm_ca<128, 128, 2, 4, false, false, true, false>
        <<<dim3(4, 4, BATCH), 256, SM_128_NN>>>(
        cWout, U, Mm, nullptr, CDIM, CDIM, CDIM,
        0, 0, CC, 0, CC, 0, 1, 1.0f);

    // 7) out[b] = M[b] @ cn[b] + bout  (NN, K=512, bias), 256x128 tiles
    tf32gemm_ca<256, 128, 4, 2, false, true, false, false>
        <<<dim3(32, 2, BATCH), 256, SM_256_NN>>>(
        Mm, cn, out, bout, CDIM, NSP, CDIM,
        CC, 0, CF, 0, CF, 0, 1, 1.0f);
}